// round 3
// baseline (speedup 1.0000x reference)
#include <cuda_runtime.h>
#include <cuda_fp16.h>
#include <cstdint>

#define K_DIM 1024
#define N_DIM 1024
#define BM 128
#define BN 256
#define BK 32
#define NSTAGES (K_DIM / BK)        // 32
#define THREADS 256
#define APITCH 80                    // 64B data + 16B pad: conflict-free ldmatrix
#define A_BYTES (BM * APITCH)        // 10240
#define B_BYTES (BN * APITCH)        // 20480
#define STAGE_BYTES (A_BYTES + B_BYTES)  // 30720
#define SMEM_TOTAL (2 * STAGE_BYTES)     // 61440

// ---- device-global scratch (allocation-free) ----
__device__ float g_partial[1024];
__device__ float g_scale;
__device__ __align__(256) __half g_wq[N_DIM * K_DIM];  // ternary weights fp16 [out,in]

__device__ __forceinline__ uint32_t smem_u32(const void* p) {
    uint32_t a;
    asm("{ .reg .u64 t; cvta.to.shared.u64 t, %1; cvt.u32.u64 %0, t; }"
        : "=r"(a) : "l"(p));
    return a;
}

__device__ __forceinline__ void ldsm_x4(uint32_t* r, uint32_t addr) {
    asm volatile("ldmatrix.sync.aligned.m8n8.x4.shared.b16 {%0,%1,%2,%3}, [%4];"
                 : "=r"(r[0]), "=r"(r[1]), "=r"(r[2]), "=r"(r[3]) : "r"(addr));
}
__device__ __forceinline__ void mma16816(float* c, const uint32_t* a, uint32_t b0, uint32_t b1) {
    asm volatile(
        "mma.sync.aligned.m16n8k16.row.col.f32.f16.f16.f32 "
        "{%0,%1,%2,%3}, {%4,%5,%6,%7}, {%8,%9}, {%0,%1,%2,%3};"
        : "+f"(c[0]), "+f"(c[1]), "+f"(c[2]), "+f"(c[3])
        : "r"(a[0]), "r"(a[1]), "r"(a[2]), "r"(a[3]), "r"(b0), "r"(b1));
}

// ============================ pre-kernels ============================

__global__ void k_absmean(const float* __restrict__ w) {
    __shared__ float red[256];
    int t = threadIdx.x;
    float4 v = *(const float4*)(w + (size_t)blockIdx.x * 1024 + t * 4);
    red[t] = fabsf(v.x) + fabsf(v.y) + fabsf(v.z) + fabsf(v.w);
    __syncthreads();
    for (int o = 128; o > 0; o >>= 1) {
        if (t < o) red[t] += red[t + o];
        __syncthreads();
    }
    if (t == 0) g_partial[blockIdx.x] = red[0];
}

__global__ void k_scale() {
    __shared__ float red[256];
    int t = threadIdx.x;
    red[t] = g_partial[t] + g_partial[t + 256] + g_partial[t + 512] + g_partial[t + 768];
    __syncthreads();
    for (int o = 128; o > 0; o >>= 1) {
        if (t < o) red[t] += red[t + o];
        __syncthreads();
    }
    if (t == 0) g_scale = fmaxf(red[0] / 1048576.0f, 1e-5f);
}

__global__ void k_quant(const float* __restrict__ w) {
    int i = (blockIdx.x * 256 + threadIdx.x) * 4;
    float s = g_scale;
    float4 v = *(const float4*)(w + i);
    float q0 = fminf(fmaxf(rintf(v.x / s), -1.0f), 1.0f);
    float q1 = fminf(fmaxf(rintf(v.y / s), -1.0f), 1.0f);
    float q2 = fminf(fmaxf(rintf(v.z / s), -1.0f), 1.0f);
    float q3 = fminf(fmaxf(rintf(v.w / s), -1.0f), 1.0f);
    __half2 h0 = __floats2half2_rn(q0, q1);
    __half2 h1 = __floats2half2_rn(q2, q3);
    uint2 u;
    u.x = *reinterpret_cast<uint32_t*>(&h0);
    u.y = *reinterpret_cast<uint32_t*>(&h1);
    *(uint2*)(g_wq + i) = u;
}

// ============================ GEMM ============================

__global__ void __launch_bounds__(THREADS, 1)
bitlinear_gemm(const float* __restrict__ x, float* __restrict__ out) {
    extern __shared__ __align__(128) char smem[];
    uint32_t sb = smem_u32(smem);
    int tid = threadIdx.x, lane = tid & 31, wid = tid >> 5;
    int wm = wid & 1, wn = wid >> 1;
    int n0 = blockIdx.x * BN, m0 = blockIdx.y * BM;

    const float*  xa = x + (size_t)m0 * K_DIM;
    const __half* wb = g_wq + (size_t)n0 * K_DIM;

    // per-thread staging addresses
    int arow = tid >> 1, aseg = tid & 1;
    const float*  aptr = xa + (size_t)arow * K_DIM + aseg * 16;
    const __half* bptr = wb + (size_t)tid * K_DIM;
    int a_sts = arow * APITCH + aseg * 32;          // byte offset in A region
    int b_sts = A_BYTES + tid * APITCH;             // byte offset in B region

    // ldmatrix source addresses (byte offsets added per stage/kstep)
    // A: frag0 lanes0-7 rows/k0, frag1 lanes8-15 rows+8/k0, frag2 rows/k8, frag3 rows+8/k8
    uint32_t a_ld[4], b_ld[4];
    #pragma unroll
    for (int mt = 0; mt < 4; mt++)
        a_ld[mt] = sb + (wm * 64 + mt * 16 + (lane & 15)) * APITCH + (lane >> 4) * 16;
    // B (non-trans, n-rows): frag0 = n0-7/k0, frag1 = n0-7/k8, frag2 = n8-15/k0, frag3 = n8-15/k8
    #pragma unroll
    for (int np = 0; np < 4; np++)
        b_ld[np] = sb + A_BYTES
                 + (wn * 64 + np * 16 + (lane & 7) + ((lane >> 4) & 1) * 8) * APITCH
                 + ((lane >> 3) & 1) * 16;

    float acc[4][8][4];
    #pragma unroll
    for (int i = 0; i < 4; i++)
        #pragma unroll
        for (int j = 0; j < 8; j++)
            #pragma unroll
            for (int k = 0; k < 4; k++) acc[i][j][k] = 0.0f;

    // ---- prologue: stage 0 ----
    {
        float4 astg[4]; uint4 bstg[4];
        #pragma unroll
        for (int i = 0; i < 4; i++) astg[i] = *(const float4*)(aptr + i * 4);
        #pragma unroll
        for (int i = 0; i < 4; i++) bstg[i] = *(const uint4*)((const char*)bptr + i * 16);
        #pragma unroll
        for (int h = 0; h < 2; h++) {
            __half2 p0 = __floats2half2_rn(astg[2*h].x, astg[2*h].y);
            __half2 p1 = __floats2half2_rn(astg[2*h].z, astg[2*h].w);
            __half2 p2 = __floats2half2_rn(astg[2*h+1].x, astg[2*h+1].y);
            __half2 p3 = __floats2half2_rn(astg[2*h+1].z, astg[2*h+1].w);
            uint4 u;
            u.x = *(uint32_t*)&p0; u.y = *(uint32_t*)&p1;
            u.z = *(uint32_t*)&p2; u.w = *(uint32_t*)&p3;
            *(uint4*)(smem + a_sts + h * 16) = u;
        }
        #pragma unroll
        for (int i = 0; i < 4; i++) *(uint4*)(smem + b_sts + i * 16) = bstg[i];
    }
    __syncthreads();

    // ---- main loop ----
    #pragma unroll 1
    for (int s = 0; s < NSTAGES; s++) {
        uint32_t ab = (s & 1) * STAGE_BYTES;

        float4 astg[4]; uint4 bstg[4];
        if (s + 1 < NSTAGES) {
            int k0 = (s + 1) * BK;
            #pragma unroll
            for (int i = 0; i < 4; i++) astg[i] = *(const float4*)(aptr + k0 + i * 4);
            #pragma unroll
            for (int i = 0; i < 4; i++)
                bstg[i] = *(const uint4*)((const char*)bptr + k0 * 2 + i * 16);
        }

        // compute: 2 k16 steps
        #pragma unroll
        for (int ks = 0; ks < 2; ks++) {
            uint32_t a[4][4];
            #pragma unroll
            for (int mt = 0; mt < 4; mt++) ldsm_x4(a[mt], a_ld[mt] + ab + ks * 32);
            #pragma unroll
            for (int np = 0; np < 4; np++) {
                uint32_t b[4];
                ldsm_x4(b, b_ld[np] + ab + ks * 32);
                #pragma unroll
                for (int mt = 0; mt < 4; mt++) {
                    mma16816(acc[mt][2 * np],     a[mt], b[0], b[1]);
                    mma16816(acc[mt][2 * np + 1], a[mt], b[2], b[3]);
                }
            }
        }

        if (s + 1 < NSTAGES) {
            int nb = ((s + 1) & 1) * STAGE_BYTES;
            #pragma unroll
            for (int h = 0; h < 2; h++) {
                __half2 p0 = __floats2half2_rn(astg[2*h].x, astg[2*h].y);
                __half2 p1 = __floats2half2_rn(astg[2*h].z, astg[2*h].w);
                __half2 p2 = __floats2half2_rn(astg[2*h+1].x, astg[2*h+1].y);
                __half2 p3 = __floats2half2_rn(astg[2*h+1].z, astg[2*h+1].w);
                uint4 u;
                u.x = *(uint32_t*)&p0; u.y = *(uint32_t*)&p1;
                u.z = *(uint32_t*)&p2; u.w = *(uint32_t*)&p3;
                *(uint4*)(smem + nb + a_sts + h * 16) = u;
            }
            #pragma unroll
            for (int i = 0; i < 4; i++)
                *(uint4*)(smem + nb + b_sts + i * 16) = bstg[i];
        }
        __syncthreads();
    }

    // ---- epilogue ----
    float sc = g_scale;
    int row_base = m0 + wm * 64 + (lane >> 2);
    int col_base = n0 + wn * 64 + (lane & 3) * 2;
    #pragma unroll
    for (int mt = 0; mt < 4; mt++) {
        #pragma unroll
        for (int nt = 0; nt < 8; nt++) {
            float2 v0, v1;
            v0.x = acc[mt][nt][0] * sc; v0.y = acc[mt][nt][1] * sc;
            v1.x = acc[mt][nt][2] * sc; v1.y = acc[mt][nt][3] * sc;
            size_t r0 = (size_t)(row_base + mt * 16) * N_DIM + col_base + nt * 8;
            size_t r1 = r0 + 8 * N_DIM;
            *(float2*)(out + r0) = v0;
            *(float2*)(out + r1) = v1;
        }
    }
}

// ============================ launch ============================

extern "C" void kernel_launch(void* const* d_in, const int* in_sizes, int n_in,
                              void* d_out, int out_size) {
    const float* x = (const float*)d_in[0];
    const float* w = (const float*)d_in[1];
    float* out = (float*)d_out;
    int M = in_sizes[0] / K_DIM;   // 65536

    cudaFuncSetAttribute(bitlinear_gemm,
                         cudaFuncAttributeMaxDynamicSharedMemorySize, SMEM_TOTAL);

    k_absmean<<<1024, 256>>>(w);
    k_scale<<<1, 256>>>();
    k_quant<<<1024, 256>>>(w);

    dim3 grid(N_DIM / BN, M / BM);   // (4, 512)
    bitlinear_gemm<<<grid, THREADS, SMEM_TOTAL>>>(x, out);
}

// round 4
// speedup vs baseline: 1.2358x; 1.2358x over previous
#include <cuda_runtime.h>
#include <cuda_fp16.h>
#include <cstdint>

#define K_DIM 1024
#define N_DIM 1024
#define M_DIM 65536
#define BM 128
#define BN 256
#define BK 64
#define NSTAGES (K_DIM / BK)        // 16
#define PIPE 4                       // cp.async pipeline depth
#define THREADS 256
#define PITCH 144                    // 128B data + 16B pad (conflict-free ldmatrix)
#define A_OFF 0
#define A_BYTES (BM * PITCH)         // 18432
#define B_OFF A_BYTES
#define B_BYTES (BN * PITCH)         // 36864
#define STAGE_BYTES (A_BYTES + B_BYTES)   // 55296
#define SMEM_TOTAL (PIPE * STAGE_BYTES)   // 221184

// ---- device-global scratch (allocation-free) ----
__device__ float g_partial[1024];
__device__ float g_scale;
__device__ __align__(256) __half g_wq[N_DIM * K_DIM];        // ternary W, fp16
__device__ __align__(256) __half g_xh[(size_t)M_DIM * K_DIM]; // X converted to fp16

__device__ __forceinline__ uint32_t smem_u32(const void* p) {
    uint32_t a;
    asm("{ .reg .u64 t; cvta.to.shared.u64 t, %1; cvt.u32.u64 %0, t; }"
        : "=r"(a) : "l"(p));
    return a;
}
__device__ __forceinline__ void cp16(uint32_t dst, const void* src) {
    asm volatile("cp.async.cg.shared.global [%0], [%1], 16;" :: "r"(dst), "l"(src));
}
__device__ __forceinline__ void cp_commit() {
    asm volatile("cp.async.commit_group;");
}
template <int N>
__device__ __forceinline__ void cp_wait() {
    asm volatile("cp.async.wait_group %0;" :: "n"(N));
}
__device__ __forceinline__ void ldsm_x4(uint32_t* r, uint32_t addr) {
    asm volatile("ldmatrix.sync.aligned.m8n8.x4.shared.b16 {%0,%1,%2,%3}, [%4];"
                 : "=r"(r[0]), "=r"(r[1]), "=r"(r[2]), "=r"(r[3]) : "r"(addr));
}
__device__ __forceinline__ void mma16816(float* c, const uint32_t* a, uint32_t b0, uint32_t b1) {
    asm volatile(
        "mma.sync.aligned.m16n8k16.row.col.f32.f16.f16.f32 "
        "{%0,%1,%2,%3}, {%4,%5,%6,%7}, {%8,%9}, {%0,%1,%2,%3};"
        : "+f"(c[0]), "+f"(c[1]), "+f"(c[2]), "+f"(c[3])
        : "r"(a[0]), "r"(a[1]), "r"(a[2]), "r"(a[3]), "r"(b0), "r"(b1));
}

// ============================ pre-kernels ============================

__global__ void k_absmean(const float* __restrict__ w) {
    __shared__ float red[256];
    int t = threadIdx.x;
    float4 v = *(const float4*)(w + (size_t)blockIdx.x * 1024 + t * 4);
    red[t] = fabsf(v.x) + fabsf(v.y) + fabsf(v.z) + fabsf(v.w);
    __syncthreads();
    for (int o = 128; o > 0; o >>= 1) {
        if (t < o) red[t] += red[t + o];
        __syncthreads();
    }
    if (t == 0) g_partial[blockIdx.x] = red[0];
}

__global__ void k_scale() {
    __shared__ float red[256];
    int t = threadIdx.x;
    red[t] = g_partial[t] + g_partial[t + 256] + g_partial[t + 512] + g_partial[t + 768];
    __syncthreads();
    for (int o = 128; o > 0; o >>= 1) {
        if (t < o) red[t] += red[t + o];
        __syncthreads();
    }
    if (t == 0) g_scale = fmaxf(red[0] / 1048576.0f, 1e-5f);
}

__global__ void k_quant(const float* __restrict__ w) {
    int i = (blockIdx.x * 256 + threadIdx.x) * 4;
    float s = g_scale;
    float4 v = *(const float4*)(w + i);
    float q0 = fminf(fmaxf(rintf(v.x / s), -1.0f), 1.0f);
    float q1 = fminf(fmaxf(rintf(v.y / s), -1.0f), 1.0f);
    float q2 = fminf(fmaxf(rintf(v.z / s), -1.0f), 1.0f);
    float q3 = fminf(fmaxf(rintf(v.w / s), -1.0f), 1.0f);
    __half2 h0 = __floats2half2_rn(q0, q1);
    __half2 h1 = __floats2half2_rn(q2, q3);
    uint2 u;
    u.x = *reinterpret_cast<uint32_t*>(&h0);
    u.y = *reinterpret_cast<uint32_t*>(&h1);
    *(uint2*)(g_wq + i) = u;
}

// X fp32 -> fp16, 8 elements/thread
__global__ void k_xconv(const float* __restrict__ x) {
    size_t i = ((size_t)blockIdx.x * 256 + threadIdx.x) * 8;
    float4 v0 = *(const float4*)(x + i);
    float4 v1 = *(const float4*)(x + i + 4);
    __half2 h0 = __floats2half2_rn(v0.x, v0.y);
    __half2 h1 = __floats2half2_rn(v0.z, v0.w);
    __half2 h2 = __floats2half2_rn(v1.x, v1.y);
    __half2 h3 = __floats2half2_rn(v1.z, v1.w);
    uint4 u;
    u.x = *(uint32_t*)&h0; u.y = *(uint32_t*)&h1;
    u.z = *(uint32_t*)&h2; u.w = *(uint32_t*)&h3;
    *(uint4*)(g_xh + i) = u;
}

// ============================ GEMM ============================

__global__ void __launch_bounds__(THREADS, 1)
bitlinear_gemm(float* __restrict__ out) {
    extern __shared__ __align__(128) char smem[];
    uint32_t sb = smem_u32(smem);
    int tid = threadIdx.x, lane = tid & 31, wid = tid >> 5;
    int wm = wid & 1, wn = wid >> 1;
    int n0 = blockIdx.x * BN, m0 = blockIdx.y * BM;

    // per-thread cp.async source/dest (row = idx/8, col16 = idx%8)
    int arow = tid >> 3, acol = tid & 7;
    const __half* asrc = g_xh + (size_t)(m0 + arow) * K_DIM + acol * 8;
    const __half* bsrc = g_wq + (size_t)(n0 + arow) * K_DIM + acol * 8;
    uint32_t adst = sb + A_OFF + arow * PITCH + acol * 16;
    uint32_t bdst = sb + B_OFF + arow * PITCH + acol * 16;

    // ldmatrix addresses
    uint32_t a_ld[4], b_ld[4];
    #pragma unroll
    for (int mt = 0; mt < 4; mt++)
        a_ld[mt] = sb + A_OFF + (wm * 64 + mt * 16 + (lane & 15)) * PITCH + (lane >> 4) * 16;
    #pragma unroll
    for (int np = 0; np < 4; np++)
        b_ld[np] = sb + B_OFF
                 + (wn * 64 + np * 16 + (lane & 7) + ((lane >> 4) & 1) * 8) * PITCH
                 + ((lane >> 3) & 1) * 16;

    float acc[4][8][4];
    #pragma unroll
    for (int i = 0; i < 4; i++)
        #pragma unroll
        for (int j = 0; j < 8; j++)
            #pragma unroll
            for (int k = 0; k < 4; k++) acc[i][j][k] = 0.0f;

    // ---- prologue: issue stages 0..PIPE-2 ----
    #pragma unroll
    for (int p = 0; p < PIPE - 1; p++) {
        uint32_t ab = p * STAGE_BYTES;
        int k0 = p * BK;
        #pragma unroll
        for (int i = 0; i < 4; i++) {       // A: 1024 cp16, 4/thread (rows 0..127, 32 rows/iter)
            int ro = i * 32;
            cp16(adst + ab + ro * PITCH, asrc + (size_t)ro * K_DIM + k0);
        }
        #pragma unroll
        for (int i = 0; i < 8; i++) {       // B: 2048 cp16, 8/thread
            int ro = i * 32;
            cp16(bdst + ab + ro * PITCH, bsrc + (size_t)ro * K_DIM + k0);
        }
        cp_commit();
    }

    // ---- main loop ----
    #pragma unroll 1
    for (int s = 0; s < NSTAGES; s++) {
        cp_wait<PIPE - 2>();      // stage s resident
        __syncthreads();

        // issue stage s+PIPE-1
        if (s + PIPE - 1 < NSTAGES) {
            int p = s + PIPE - 1;
            uint32_t ab = (p & (PIPE - 1)) * STAGE_BYTES;
            int k0 = p * BK;
            #pragma unroll
            for (int i = 0; i < 4; i++) {
                int ro = i * 32;
                cp16(adst + ab + ro * PITCH, asrc + (size_t)ro * K_DIM + k0);
            }
            #pragma unroll
            for (int i = 0; i < 8; i++) {
                int ro = i * 32;
                cp16(bdst + ab + ro * PITCH, bsrc + (size_t)ro * K_DIM + k0);
            }
        }
        cp_commit();

        // compute stage s: 4 k16 steps
        uint32_t ab = (s & (PIPE - 1)) * STAGE_BYTES;
        #pragma unroll
        for (int ks = 0; ks < 4; ks++) {
            uint32_t a[4][4];
            #pragma unroll
            for (int mt = 0; mt < 4; mt++) ldsm_x4(a[mt], a_ld[mt] + ab + ks * 32);
            #pragma unroll
            for (int np = 0; np < 4; np++) {
                uint32_t b[4];
                ldsm_x4(b, b_ld[np] + ab + ks * 32);
                #pragma unroll
                for (int mt = 0; mt < 4; mt++) {
                    mma16816(acc[mt][2 * np],     a[mt], b[0], b[1]);
                    mma16816(acc[mt][2 * np + 1], a[mt], b[2], b[3]);
                }
            }
        }
        __syncthreads();
    }

    // ---- epilogue ----
    float sc = g_scale;
    int row_base = m0 + wm * 64 + (lane >> 2);
    int col_base = n0 + wn * 64 + (lane & 3) * 2;
    #pragma unroll
    for (int mt = 0; mt < 4; mt++) {
        #pragma unroll
        for (int nt = 0; nt < 8; nt++) {
            float2 v0, v1;
            v0.x = acc[mt][nt][0] * sc; v0.y = acc[mt][nt][1] * sc;
            v1.x = acc[mt][nt][2] * sc; v1.y = acc[mt][nt][3] * sc;
            size_t r0 = (size_t)(row_base + mt * 16) * N_DIM + col_base + nt * 8;
            size_t r1 = r0 + 8 * N_DIM;
            *(float2*)(out + r0) = v0;
            *(float2*)(out + r1) = v1;
        }
    }
}

// ============================ launch ============================

extern "C" void kernel_launch(void* const* d_in, const int* in_sizes, int n_in,
                              void* d_out, int out_size) {
    const float* x = (const float*)d_in[0];
    const float* w = (const float*)d_in[1];
    float* out = (float*)d_out;
    int M = in_sizes[0] / K_DIM;   // 65536

    cudaFuncSetAttribute(bitlinear_gemm,
                         cudaFuncAttributeMaxDynamicSharedMemorySize, SMEM_TOTAL);

    k_absmean<<<1024, 256>>>(w);
    k_scale<<<1, 256>>>();
    k_quant<<<1024, 256>>>(w);
    k_xconv<<<(int)(((size_t)M * K_DIM) / (256 * 8)), 256>>>(x);

    dim3 grid(N_DIM / BN, M / BM);   // (4, 512)
    bitlinear_gemm<<<grid, THREADS, SMEM_TOTAL>>>(out);
}